// round 15
// baseline (speedup 1.0000x reference)
#include <cuda_runtime.h>
#include <cuda_fp16.h>
#include <cstdint>

// Problem constants (fixed shapes)
#define M_DIM 8192      // B*S
#define N_DIM 4096      // OUT
#define K_DIM 4096      // IN
#define NUM_V 1024      // IN/4
#define LUT_SIZE 256

// Scratch (sanctioned __device__ globals)
__device__ __half g_Xh[(size_t)M_DIM * K_DIM];   // fp16-rounded x      (64 MB)
__device__ __half g_Wh[(size_t)N_DIM * K_DIM];   // reconstructed W[N][K] (32 MB)

// ---------------------------------------------------------------------------
// Kernel 1: merged prep (at DRAM floor; unchanged)
// ---------------------------------------------------------------------------
#define REC_BLOCKS 2048                            // 64 o-blocks x 32 v-blocks
#define RX_BLOCKS  ((M_DIM * K_DIM / 4) / 2048)    // 4096 (256 thr * 8 float4)
__global__ void prep_kernel(const float4* __restrict__ x,
                            const int* __restrict__ index,
                            const float* __restrict__ luts,
                            const float* __restrict__ scales) {
    __shared__ uint2 smem_t[32][65];   // [v_local][o_local], padded
    const int bid = blockIdx.x;
    const int tid = threadIdx.x;
    if (bid < REC_BLOCKS) {
        const int o0 = (bid & 63) * 64;
        const int v0 = (bid >> 6) * 32;
        const int ol = tid & 63;       // 0..63
        const int vg = tid >> 6;       // 0..3
        const int o  = o0 + ol;

        const float s = scales[(size_t)o * (K_DIM / 128) + (v0 >> 5)];

        int i0[8], i1[8];
        #pragma unroll
        for (int i = 0; i < 8; i++) {
            const int v = v0 + vg * 8 + i;
            i0[i] = index[(size_t)v * N_DIM + o];
            i1[i] = index[((size_t)NUM_V + v) * N_DIM + o];
        }
        float4 a[8], b[8];
        #pragma unroll
        for (int i = 0; i < 8; i++) {
            const int v = v0 + vg * 8 + i;
            a[i] = reinterpret_cast<const float4*>(luts)[(size_t)v * LUT_SIZE + i0[i]];
            b[i] = reinterpret_cast<const float4*>(luts)[((size_t)NUM_V + v) * LUT_SIZE + i1[i]];
        }
        #pragma unroll
        for (int i = 0; i < 8; i++) {
            const int vl = vg * 8 + i;
            __half2 h0 = __float22half2_rn(make_float2((a[i].x + b[i].x) * s, (a[i].y + b[i].y) * s));
            __half2 h1 = __float22half2_rn(make_float2((a[i].z + b[i].z) * s, (a[i].w + b[i].w) * s));
            uint2 w;
            w.x = *reinterpret_cast<uint32_t*>(&h0);
            w.y = *reinterpret_cast<uint32_t*>(&h1);
            smem_t[vl][ol] = w;
        }
        __syncthreads();

        const int warp = tid >> 5;
        const int lane = tid & 31;
        #pragma unroll
        for (int r = warp; r < 64; r += 8) {
            uint2 w = smem_t[lane][r];
            reinterpret_cast<uint2*>(g_Wh)[(size_t)(o0 + r) * NUM_V + v0 + lane] = w;
        }
    } else {
        size_t base = (size_t)(bid - REC_BLOCKS) * 2048 + tid;
        float4 v0 = __ldcs(x + base);
        float4 v1 = __ldcs(x + base + 256);
        float4 v2 = __ldcs(x + base + 512);
        float4 v3 = __ldcs(x + base + 768);
        float4 va[4] = {v0, v1, v2, v3};
        float4 v4 = __ldcs(x + base + 1024);
        float4 v5 = __ldcs(x + base + 1280);
        float4 v6 = __ldcs(x + base + 1536);
        float4 v7 = __ldcs(x + base + 1792);
        float4 vb[4] = {v4, v5, v6, v7};

        #pragma unroll
        for (int it = 0; it < 4; it++) {
            __half2 h0 = __float22half2_rn(make_float2(va[it].x, va[it].y));
            __half2 h1 = __float22half2_rn(make_float2(va[it].z, va[it].w));
            uint2 o;
            o.x = *reinterpret_cast<uint32_t*>(&h0);
            o.y = *reinterpret_cast<uint32_t*>(&h1);
            reinterpret_cast<uint2*>(g_Xh)[base + it * 256] = o;
        }
        #pragma unroll
        for (int it = 0; it < 4; it++) {
            __half2 h0 = __float22half2_rn(make_float2(vb[it].x, vb[it].y));
            __half2 h1 = __float22half2_rn(make_float2(vb[it].z, vb[it].w));
            uint2 o;
            o.x = *reinterpret_cast<uint32_t*>(&h0);
            o.y = *reinterpret_cast<uint32_t*>(&h1);
            reinterpret_cast<uint2*>(g_Xh)[base + 1024 + it * 256] = o;
        }
    }
}

// ---------------------------------------------------------------------------
// Kernel 2: fp16 GEMM, mma.sync m16n8k16 + ldmatrix + cp.async 3-stage pipe.
// C[M,N] = A[M,K] * B[N,K]^T + bias   (fp32 accumulate, fp32 out)
// CTA tile 128x128, BK=64, 8 warps (2Mx4N), warp tile 64x32, 2 CTAs/SM.
// CHANGE vs R14: prefetch split into two 4-deep cp.async bursts — A-half
// after ks=0, B-half (+commit) after ks=1 — so no ldmatrix batch queues
// behind more than 4 cp.async per thread on the LSU.
// ---------------------------------------------------------------------------
#define TM 128
#define TN 128
#define BK 64
#define PIPE 3
#define NSTAGE (K_DIM / BK)              // 64
#define STAGE_A_BYTES (TM * BK * 2)      // 16384
#define STAGE_BYTES (2 * STAGE_A_BYTES)  // 32768 (A then B)
#define SMEM_TOTAL (PIPE * STAGE_BYTES)  // 98304

__device__ __forceinline__ void cp16s(uint32_t sa, const void* g) {
    asm volatile("cp.async.cg.shared.global [%0], [%1], 16;\n" :: "r"(sa), "l"(g));
}

__device__ __forceinline__ void ldsm_x4(uint32_t r[4], uint32_t addr) {
    asm volatile("ldmatrix.sync.aligned.m8n8.x4.shared.b16 {%0,%1,%2,%3}, [%4];"
                 : "=r"(r[0]), "=r"(r[1]), "=r"(r[2]), "=r"(r[3]) : "r"(addr));
}

__device__ __forceinline__ void mma_f16(float c[4], const uint32_t a[4],
                                        uint32_t b0, uint32_t b1) {
    asm volatile(
        "mma.sync.aligned.m16n8k16.row.col.f32.f16.f16.f32 "
        "{%0,%1,%2,%3}, {%4,%5,%6,%7}, {%8,%9}, {%0,%1,%2,%3};\n"
        : "+f"(c[0]), "+f"(c[1]), "+f"(c[2]), "+f"(c[3])
        : "r"(a[0]), "r"(a[1]), "r"(a[2]), "r"(a[3]), "r"(b0), "r"(b1));
}

__global__ __launch_bounds__(256, 2)
void gemm_f16_kernel(const float* __restrict__ bias, float* __restrict__ C) {
    extern __shared__ char smem_raw[];
    const uint32_t smem = (uint32_t)__cvta_generic_to_shared(smem_raw);
    const int tid  = threadIdx.x;
    const int warp = tid >> 5;
    const int lane = tid & 31;
    const int wm   = warp >> 2;   // 0..1 : 64 M rows
    const int wn   = warp & 3;    // 0..3 : 32 N cols

    // --- raster: groups of 512 CTAs = 64 M-tiles x 8 N-tiles ---
    const int bid = blockIdx.x;
    const int gid = bid >> 9;
    const int rr  = bid & 511;
    const size_t m0 = (size_t)(rr >> 3) * TM;
    const size_t n0 = (size_t)((gid << 3) + (rr & 7)) * TN;

    // --- loader geometry: thread -> (row = tid>>3, 16B-col = tid&7) ---
    const int lrow = tid >> 3;          // 0..31
    const int lcg  = tid & 7;           // 0..7
    const uint32_t sdst = (uint32_t)(lrow * 128 + ((lcg ^ (lrow & 7)) * 16));
    const __half* gA0 = g_Xh + (m0 + lrow) * K_DIM + lcg * 8;
    const __half* gB0 = g_Wh + (n0 + lrow) * K_DIM + lcg * 8;

    // A-half: the A operand tile (4 cp.async per thread)
    #define LOAD_STAGE_A(st, buf)                                                 \
        {                                                                         \
            const __half* ga = gA0 + (st) * BK;                                   \
            uint32_t sa = smem + (buf) * STAGE_BYTES + sdst;                      \
            _Pragma("unroll")                                                     \
            for (int i = 0; i < 4; i++)                                           \
                cp16s(sa + i * (32 * 128), ga + (size_t)i * 32 * K_DIM);          \
        }
    // B-half: the B operand tile + the stage's single commit
    #define LOAD_STAGE_B(st, buf)                                                 \
        {                                                                         \
            const __half* gb = gB0 + (st) * BK;                                   \
            uint32_t sb = smem + (buf) * STAGE_BYTES + STAGE_A_BYTES + sdst;      \
            _Pragma("unroll")                                                     \
            for (int i = 0; i < 4; i++)                                           \
                cp16s(sb + i * (32 * 128), gb + (size_t)i * 32 * K_DIM);          \
            asm volatile("cp.async.commit_group;\n" ::);                          \
        }

    // --- fragment-load geometry (ldmatrix) ---
    const int aRow  = wm * 64 + (lane & 15);
    const int aKsel = lane >> 4;                 // 0/1
    const uint32_t aBase = (uint32_t)(aRow * 128);
    const int aXor  = aRow & 7;
    const int nRow  = wn * 32 + (lane & 7) + ((lane >> 4) << 3);
    const int bKsel = (lane >> 3) & 1;
    const uint32_t bBase = (uint32_t)(STAGE_A_BYTES + nRow * 128);
    const int bXor  = nRow & 7;

    float acc[4][4][4];
    #pragma unroll
    for (int i = 0; i < 4; i++)
        #pragma unroll
        for (int j = 0; j < 4; j++)
            #pragma unroll
            for (int r = 0; r < 4; r++) acc[i][j][r] = 0.0f;

    // one ks-step: frag loads + 16 MMAs
    #define KS_STEP(ks)                                                           \
        {                                                                         \
            uint32_t af[4][4];                                                    \
            _Pragma("unroll")                                                     \
            for (int mi = 0; mi < 4; mi++) {                                      \
                uint32_t addr = sbase + aBase + mi * (16 * 128)                   \
                              + (uint32_t)(((((ks) * 2 + aKsel) ^ aXor)) * 16);   \
                ldsm_x4(af[mi], addr);                                            \
            }                                                                     \
            uint32_t bf[2][4];                                                    \
            _Pragma("unroll")                                                     \
            for (int p = 0; p < 2; p++) {                                         \
                uint32_t addr = sbase + bBase + p * (16 * 128)                    \
                              + (uint32_t)(((((ks) * 2 + bKsel) ^ bXor)) * 16);   \
                ldsm_x4(bf[p], addr);                                             \
            }                                                                     \
            _Pragma("unroll")                                                     \
            for (int mi = 0; mi < 4; mi++) {                                      \
                _Pragma("unroll")                                                 \
                for (int ni = 0; ni < 4; ni++) {                                  \
                    mma_f16(acc[mi][ni], af[mi], bf[ni >> 1][(ni & 1) * 2],       \
                            bf[ni >> 1][(ni & 1) * 2 + 1]);                       \
                }                                                                 \
            }                                                                     \
        }

    LOAD_STAGE_A(0, 0);
    LOAD_STAGE_B(0, 0);
    LOAD_STAGE_A(1, 1);
    LOAD_STAGE_B(1, 1);

    for (int kt = 0; kt < NSTAGE; kt++) {
        const int buf = kt % PIPE;
        if (kt + 1 < NSTAGE) {
            asm volatile("cp.async.wait_group 1;\n" ::);
        } else {
            asm volatile("cp.async.wait_group 0;\n" ::);
        }
        __syncthreads();

        const uint32_t sbase = smem + buf * STAGE_BYTES;
        const int pf = (kt + 2 < NSTAGE);
        const int pbuf = (kt + 2) % PIPE;

        // ks=0 first: feed the tensor pipe immediately after the barrier
        KS_STEP(0);

        // A-half of the prefetch hides under ks=0's MMA tail / ks=1
        if (pf) { LOAD_STAGE_A(kt + 2, pbuf); }

        KS_STEP(1);

        // B-half + commit hides under ks=1's MMA tail / ks=2
        if (pf) { LOAD_STAGE_B(kt + 2, pbuf); }

        KS_STEP(2);
        KS_STEP(3);
    }

    // --- epilogue: + bias, fp32 out, streaming stores (C never re-read) ---
    const int g  = lane >> 2;
    const int t2 = (lane & 3) * 2;
    #pragma unroll
    for (int mi = 0; mi < 4; mi++) {
        size_t m = m0 + wm * 64 + mi * 16 + g;
        float* c0 = C + m * N_DIM;
        float* c1 = C + (m + 8) * N_DIM;
        #pragma unroll
        for (int ni = 0; ni < 4; ni++) {
            size_t n = n0 + wn * 32 + ni * 8 + t2;
            float b0 = bias[n], b1 = bias[n + 1];
            __stcs(reinterpret_cast<float2*>(c0 + n),
                   make_float2(acc[mi][ni][0] + b0, acc[mi][ni][1] + b1));
            __stcs(reinterpret_cast<float2*>(c1 + n),
                   make_float2(acc[mi][ni][2] + b0, acc[mi][ni][3] + b1));
        }
    }
    #undef LOAD_STAGE_A
    #undef LOAD_STAGE_B
    #undef KS_STEP
}

// ---------------------------------------------------------------------------
// Launch
// ---------------------------------------------------------------------------
extern "C" void kernel_launch(void* const* d_in, const int* in_sizes, int n_in,
                              void* d_out, int out_size) {
    const float* x      = (const float*)d_in[0];
    const int*   index  = (const int*)d_in[1];
    const float* luts   = (const float*)d_in[2];
    const float* scales = (const float*)d_in[3];
    const float* bias   = (const float*)d_in[4];
    float* out = (float*)d_out;

    prep_kernel<<<REC_BLOCKS + RX_BLOCKS, 256>>>(
        reinterpret_cast<const float4*>(x), index, luts, scales);

    {
        static int attr_set = 0;
        if (!attr_set) {
            cudaFuncSetAttribute(gemm_f16_kernel,
                                 cudaFuncAttributeMaxDynamicSharedMemorySize, SMEM_TOTAL);
            attr_set = 1;
        }
        dim3 grid((M_DIM / TM) * (N_DIM / TN));  // 2048
        gemm_f16_kernel<<<grid, 256, SMEM_TOTAL>>>(bias, out);
    }
}

// round 16
// speedup vs baseline: 1.0133x; 1.0133x over previous
#include <cuda_runtime.h>
#include <cuda_fp16.h>
#include <cstdint>

// Problem constants (fixed shapes)
#define M_DIM 8192      // B*S
#define N_DIM 4096      // OUT
#define K_DIM 4096      // IN
#define NUM_V 1024      // IN/4
#define LUT_SIZE 256

// Scratch (sanctioned __device__ globals)
__device__ __half g_Xh[(size_t)M_DIM * K_DIM];   // fp16-rounded x      (64 MB)
__device__ __half g_Wh[(size_t)N_DIM * K_DIM];   // reconstructed W[N][K] (32 MB)

// ---------------------------------------------------------------------------
// Kernel 1: merged prep (at DRAM floor; unchanged)
// ---------------------------------------------------------------------------
#define REC_BLOCKS 2048                            // 64 o-blocks x 32 v-blocks
#define RX_BLOCKS  ((M_DIM * K_DIM / 4) / 2048)    // 4096 (256 thr * 8 float4)
__global__ void prep_kernel(const float4* __restrict__ x,
                            const int* __restrict__ index,
                            const float* __restrict__ luts,
                            const float* __restrict__ scales) {
    __shared__ uint2 smem_t[32][65];   // [v_local][o_local], padded
    const int bid = blockIdx.x;
    const int tid = threadIdx.x;
    if (bid < REC_BLOCKS) {
        const int o0 = (bid & 63) * 64;
        const int v0 = (bid >> 6) * 32;
        const int ol = tid & 63;       // 0..63
        const int vg = tid >> 6;       // 0..3
        const int o  = o0 + ol;

        const float s = scales[(size_t)o * (K_DIM / 128) + (v0 >> 5)];

        int i0[8], i1[8];
        #pragma unroll
        for (int i = 0; i < 8; i++) {
            const int v = v0 + vg * 8 + i;
            i0[i] = index[(size_t)v * N_DIM + o];
            i1[i] = index[((size_t)NUM_V + v) * N_DIM + o];
        }
        float4 a[8], b[8];
        #pragma unroll
        for (int i = 0; i < 8; i++) {
            const int v = v0 + vg * 8 + i;
            a[i] = reinterpret_cast<const float4*>(luts)[(size_t)v * LUT_SIZE + i0[i]];
            b[i] = reinterpret_cast<const float4*>(luts)[((size_t)NUM_V + v) * LUT_SIZE + i1[i]];
        }
        #pragma unroll
        for (int i = 0; i < 8; i++) {
            const int vl = vg * 8 + i;
            __half2 h0 = __float22half2_rn(make_float2((a[i].x + b[i].x) * s, (a[i].y + b[i].y) * s));
            __half2 h1 = __float22half2_rn(make_float2((a[i].z + b[i].z) * s, (a[i].w + b[i].w) * s));
            uint2 w;
            w.x = *reinterpret_cast<uint32_t*>(&h0);
            w.y = *reinterpret_cast<uint32_t*>(&h1);
            smem_t[vl][ol] = w;
        }
        __syncthreads();

        const int warp = tid >> 5;
        const int lane = tid & 31;
        #pragma unroll
        for (int r = warp; r < 64; r += 8) {
            uint2 w = smem_t[lane][r];
            reinterpret_cast<uint2*>(g_Wh)[(size_t)(o0 + r) * NUM_V + v0 + lane] = w;
        }
    } else {
        size_t base = (size_t)(bid - REC_BLOCKS) * 2048 + tid;
        float4 v0 = __ldcs(x + base);
        float4 v1 = __ldcs(x + base + 256);
        float4 v2 = __ldcs(x + base + 512);
        float4 v3 = __ldcs(x + base + 768);
        float4 va[4] = {v0, v1, v2, v3};
        float4 v4 = __ldcs(x + base + 1024);
        float4 v5 = __ldcs(x + base + 1280);
        float4 v6 = __ldcs(x + base + 1536);
        float4 v7 = __ldcs(x + base + 1792);
        float4 vb[4] = {v4, v5, v6, v7};

        #pragma unroll
        for (int it = 0; it < 4; it++) {
            __half2 h0 = __float22half2_rn(make_float2(va[it].x, va[it].y));
            __half2 h1 = __float22half2_rn(make_float2(va[it].z, va[it].w));
            uint2 o;
            o.x = *reinterpret_cast<uint32_t*>(&h0);
            o.y = *reinterpret_cast<uint32_t*>(&h1);
            reinterpret_cast<uint2*>(g_Xh)[base + it * 256] = o;
        }
        #pragma unroll
        for (int it = 0; it < 4; it++) {
            __half2 h0 = __float22half2_rn(make_float2(vb[it].x, vb[it].y));
            __half2 h1 = __float22half2_rn(make_float2(vb[it].z, vb[it].w));
            uint2 o;
            o.x = *reinterpret_cast<uint32_t*>(&h0);
            o.y = *reinterpret_cast<uint32_t*>(&h1);
            reinterpret_cast<uint2*>(g_Xh)[base + 1024 + it * 256] = o;
        }
    }
}

// ---------------------------------------------------------------------------
// Kernel 2: fp16 GEMM, mma.sync m16n8k16 + ldmatrix + cp.async 3-stage pipe.
// C[M,N] = A[M,K] * B[N,K]^T + bias   (fp32 accumulate, fp32 out)
// CTA tile 128x128, BK=64, 4 warps (2Mx2N), warp tile 64x64, 128 thr,
// 2 CTAs/SM. R14 scheduling: ks=0 first, full prefetch after ks=0, one
// barrier per stage. 64x64 warp tile cuts LDSM/ks by 33% vs 64x32.
// ---------------------------------------------------------------------------
#define TM 128
#define TN 128
#define BK 64
#define PIPE 3
#define NSTAGE (K_DIM / BK)              // 64
#define STAGE_A_BYTES (TM * BK * 2)      // 16384
#define STAGE_BYTES (2 * STAGE_A_BYTES)  // 32768 (A then B)
#define SMEM_TOTAL (PIPE * STAGE_BYTES)  // 98304

__device__ __forceinline__ void cp16s(uint32_t sa, const void* g) {
    asm volatile("cp.async.cg.shared.global [%0], [%1], 16;\n" :: "r"(sa), "l"(g));
}

__device__ __forceinline__ void ldsm_x4(uint32_t r[4], uint32_t addr) {
    asm volatile("ldmatrix.sync.aligned.m8n8.x4.shared.b16 {%0,%1,%2,%3}, [%4];"
                 : "=r"(r[0]), "=r"(r[1]), "=r"(r[2]), "=r"(r[3]) : "r"(addr));
}

__device__ __forceinline__ void mma_f16(float c[4], const uint32_t a[4],
                                        uint32_t b0, uint32_t b1) {
    asm volatile(
        "mma.sync.aligned.m16n8k16.row.col.f32.f16.f16.f32 "
        "{%0,%1,%2,%3}, {%4,%5,%6,%7}, {%8,%9}, {%0,%1,%2,%3};\n"
        : "+f"(c[0]), "+f"(c[1]), "+f"(c[2]), "+f"(c[3])
        : "r"(a[0]), "r"(a[1]), "r"(a[2]), "r"(a[3]), "r"(b0), "r"(b1));
}

__global__ __launch_bounds__(128, 2)
void gemm_f16_kernel(const float* __restrict__ bias, float* __restrict__ C) {
    extern __shared__ char smem_raw[];
    const uint32_t smem = (uint32_t)__cvta_generic_to_shared(smem_raw);
    const int tid  = threadIdx.x;
    const int warp = tid >> 5;
    const int lane = tid & 31;
    const int wm   = warp >> 1;   // 0..1 : 64 M rows
    const int wn   = warp & 1;    // 0..1 : 64 N cols

    // --- raster: groups of 512 CTAs = 64 M-tiles x 8 N-tiles ---
    const int bid = blockIdx.x;
    const int gid = bid >> 9;
    const int rr  = bid & 511;
    const size_t m0 = (size_t)(rr >> 3) * TM;
    const size_t n0 = (size_t)((gid << 3) + (rr & 7)) * TN;

    // --- loader geometry: 128 thr -> (row = tid>>3, 16B-col = tid&7) ---
    // rows step 16 per iteration; 8 iterations per operand tile.
    const int lrow = tid >> 3;          // 0..15
    const int lcg  = tid & 7;           // 0..7
    const uint32_t sdst = (uint32_t)(lrow * 128 + ((lcg ^ (lrow & 7)) * 16));
    const __half* gA0 = g_Xh + (m0 + lrow) * K_DIM + lcg * 8;
    const __half* gB0 = g_Wh + (n0 + lrow) * K_DIM + lcg * 8;

    #define LOAD_STAGE(st, buf)                                                   \
        {                                                                         \
            const __half* ga = gA0 + (st) * BK;                                   \
            const __half* gb = gB0 + (st) * BK;                                   \
            uint32_t sa = smem + (buf) * STAGE_BYTES + sdst;                      \
            uint32_t sb = sa + STAGE_A_BYTES;                                     \
            _Pragma("unroll")                                                     \
            for (int i = 0; i < 8; i++) {                                         \
                cp16s(sa + i * (16 * 128), ga + (size_t)i * 16 * K_DIM);          \
                cp16s(sb + i * (16 * 128), gb + (size_t)i * 16 * K_DIM);          \
            }                                                                     \
            asm volatile("cp.async.commit_group;\n" ::);                          \
        }

    // --- fragment-load geometry (ldmatrix) ---
    const int aRow  = wm * 64 + (lane & 15);
    const int aKsel = lane >> 4;                 // 0/1
    const uint32_t aBase = (uint32_t)(aRow * 128);
    const int aXor  = aRow & 7;
    const int nRowB = wn * 64 + (lane & 7) + ((lane >> 4) << 3);
    const int bKsel = (lane >> 3) & 1;
    const int bXor  = nRowB & 7;

    float acc[4][8][4];
    #pragma unroll
    for (int i = 0; i < 4; i++)
        #pragma unroll
        for (int j = 0; j < 8; j++)
            #pragma unroll
            for (int r = 0; r < 4; r++) acc[i][j][r] = 0.0f;

    // one ks-step: 4 A-frag + 4 B-frag ldmatrix, then 32 MMAs
    #define KS_STEP(ks)                                                           \
        {                                                                         \
            uint32_t af[4][4];                                                    \
            _Pragma("unroll")                                                     \
            for (int mi = 0; mi < 4; mi++) {                                      \
                uint32_t addr = sbase + aBase + mi * (16 * 128)                   \
                              + (uint32_t)(((((ks) * 2 + aKsel) ^ aXor)) * 16);   \
                ldsm_x4(af[mi], addr);                                            \
            }                                                                     \
            uint32_t bf[4][4];                                                    \
            _Pragma("unroll")                                                     \
            for (int p = 0; p < 4; p++) {                                         \
                uint32_t addr = sbase + STAGE_A_BYTES                             \
                              + (uint32_t)((nRowB + p * 16) * 128)                \
                              + (uint32_t)(((((ks) * 2 + bKsel) ^ bXor)) * 16);   \
                ldsm_x4(bf[p], addr);                                             \
            }                                                                     \
            _Pragma("unroll")                                                     \
            for (int mi = 0; mi < 4; mi++) {                                      \
                _Pragma("unroll")                                                 \
                for (int ni = 0; ni < 8; ni++) {                                  \
                    mma_f16(acc[mi][ni], af[mi], bf[ni >> 1][(ni & 1) * 2],       \
                            bf[ni >> 1][(ni & 1) * 2 + 1]);                       \
                }                                                                 \
            }                                                                     \
        }

    LOAD_STAGE(0, 0);
    LOAD_STAGE(1, 1);

    for (int kt = 0; kt < NSTAGE; kt++) {
        const int buf = kt % PIPE;
        if (kt + 1 < NSTAGE) {
            asm volatile("cp.async.wait_group 1;\n" ::);
        } else {
            asm volatile("cp.async.wait_group 0;\n" ::);
        }
        __syncthreads();

        const uint32_t sbase = smem + buf * STAGE_BYTES;

        // ks=0 first: feed the tensor pipe immediately after the barrier
        KS_STEP(0);

        // mid-stage prefetch (R14-validated): buffer (kt+2)%3 == (kt-1)%3 was
        // last read in iteration kt-1; all warps passed the barrier above.
        if (kt + 2 < NSTAGE) {
            LOAD_STAGE(kt + 2, (kt + 2) % PIPE);
        }

        KS_STEP(1);
        KS_STEP(2);
        KS_STEP(3);
    }

    // --- epilogue: + bias, fp32 out, streaming stores (C never re-read) ---
    const int g  = lane >> 2;
    const int t2 = (lane & 3) * 2;
    #pragma unroll
    for (int mi = 0; mi < 4; mi++) {
        size_t m = m0 + wm * 64 + mi * 16 + g;
        float* c0 = C + m * N_DIM;
        float* c1 = C + (m + 8) * N_DIM;
        #pragma unroll
        for (int ni = 0; ni < 8; ni++) {
            size_t n = n0 + wn * 64 + ni * 8 + t2;
            float b0 = bias[n], b1 = bias[n + 1];
            __stcs(reinterpret_cast<float2*>(c0 + n),
                   make_float2(acc[mi][ni][0] + b0, acc[mi][ni][1] + b1));
            __stcs(reinterpret_cast<float2*>(c1 + n),
                   make_float2(acc[mi][ni][2] + b0, acc[mi][ni][3] + b1));
        }
    }
    #undef LOAD_STAGE
    #undef KS_STEP
}

// ---------------------------------------------------------------------------
// Launch
// ---------------------------------------------------------------------------
extern "C" void kernel_launch(void* const* d_in, const int* in_sizes, int n_in,
                              void* d_out, int out_size) {
    const float* x      = (const float*)d_in[0];
    const int*   index  = (const int*)d_in[1];
    const float* luts   = (const float*)d_in[2];
    const float* scales = (const float*)d_in[3];
    const float* bias   = (const float*)d_in[4];
    float* out = (float*)d_out;

    prep_kernel<<<REC_BLOCKS + RX_BLOCKS, 256>>>(
        reinterpret_cast<const float4*>(x), index, luts, scales);

    {
        static int attr_set = 0;
        if (!attr_set) {
            cudaFuncSetAttribute(gemm_f16_kernel,
                                 cudaFuncAttributeMaxDynamicSharedMemorySize, SMEM_TOTAL);
            attr_set = 1;
        }
        dim3 grid((M_DIM / TM) * (N_DIM / TN));  // 2048
        gemm_f16_kernel<<<grid, 128, SMEM_TOTAL>>>(bias, out);
    }
}